// round 11
// baseline (speedup 1.0000x reference)
#include <cuda_runtime.h>
#include <cuda_fp16.h>
#include <cstdint>

// ============================================================
// Problem dims (fixed)
// ============================================================
#define MDIM 8192     // B*S
#define NDIM 4096
#define KDIM 4096
#define NGROUPS 64    // group size 64

constexpr int TILE_M = 128;
constexpr int TILE_N = 128;
constexpr int KS = 64;                     // halves per K-stage (128 B rows)
constexpr int NKS = KDIM / KS;             // 64
constexpr int TILE_BYTES = TILE_M * 128;   // 16 KB per operand tile-stage
constexpr int NSTAGE = 3;
constexpr int STAGE_B = 2 * TILE_BYTES;    // 32 KB
constexpr int SMEM_BYTES = 2048 + NSTAGE * STAGE_B;   // pad for 1KB align + mbars

// Scratch: half tiles pre-laid-out in GEMM's per-stage swizzled format.
__device__ __half g_Wt[(size_t)NDIM * KDIM];   // 32 MB, tiles (nt*NKS + ks)
__device__ __half g_Xt[(size_t)MDIM * KDIM];   // 64 MB, tiles (mt*NKS + ks)

// ============================================================
// Pass 1 (merged): dequant W and convert X into tiled+swizzled layout.
// ============================================================
constexpr int W_BLOCKS = (int)((size_t)NDIM * KDIM * 2 / 16 / 256);   // 8192
constexpr int X_BLOCKS = (int)((size_t)MDIM * KDIM * 2 / 16 / 256);   // 32768

__global__ void __launch_bounds__(256) convert_kernel(
    const int* __restrict__ q, const float* __restrict__ scale, const float* __restrict__ zp,
    const float* __restrict__ x)
{
    if (blockIdx.x < W_BLOCKS) {
        int t = blockIdx.x * 256 + threadIdx.x;     // target 16B chunk index
        int idx = t & 1023;                         // chunk within 16KB tile
        int tile = t >> 10;                         // nt*NKS + ks
        int ks = tile & (NKS - 1);
        int nt = tile >> 6;
        int r = idx >> 3;
        int cS = idx & 7;
        int c = cS ^ (r & 7);                       // un-swizzled chunk
        int n = nt * 128 + r;
        int k = ks * KS + c * 8;
        const int4* qp = reinterpret_cast<const int4*>(q + (size_t)n * KDIM + k);
        int4 q0 = qp[0], q1 = qp[1];
        float s = scale[n * NGROUPS + ks];          // group == ks (G == KS == 64)
        float z = zp[n * NGROUPS + ks];
        __half2 h[4];
        h[0] = __floats2half2_rn(((float)q0.x - z) * s, ((float)q0.y - z) * s);
        h[1] = __floats2half2_rn(((float)q0.z - z) * s, ((float)q0.w - z) * s);
        h[2] = __floats2half2_rn(((float)q1.x - z) * s, ((float)q1.y - z) * s);
        h[3] = __floats2half2_rn(((float)q1.z - z) * s, ((float)q1.w - z) * s);
        reinterpret_cast<uint4*>(g_Wt)[t] = *reinterpret_cast<uint4*>(h);
    } else {
        int t = (blockIdx.x - W_BLOCKS) * 256 + threadIdx.x;
        int idx = t & 1023;
        int tile = t >> 10;                         // mt*NKS + ks
        int ks = tile & (NKS - 1);
        int mt = tile >> 6;
        int r = idx >> 3;
        int cS = idx & 7;
        int c = cS ^ (r & 7);
        int m = mt * 128 + r;
        int k = ks * KS + c * 8;
        const float4* xp = reinterpret_cast<const float4*>(x + (size_t)m * KDIM + k);
        float4 a = xp[0], b = xp[1];
        __half2 h[4];
        h[0] = __floats2half2_rn(a.x, a.y);
        h[1] = __floats2half2_rn(a.z, a.w);
        h[2] = __floats2half2_rn(b.x, b.y);
        h[3] = __floats2half2_rn(b.z, b.w);
        reinterpret_cast<uint4*>(g_Xt)[t] = *reinterpret_cast<uint4*>(h);
    }
}

// ============================================================
// Pass 2: GEMM  out[M,N] = X @ W^T + bias   (fp16 in, fp32 acc)
// CTA 128x128 + dedicated producer warp (288 threads), 8 consumer warps
// (warp 64x32), 3-stage mbarrier ring, NO __syncthreads in steady state.
// Producer: waits empty (8 warp-arrivals), issues 2 x 16KB cp.async.bulk.
// Consumers: wait full; cross-stage kk0 fragment prefetch during kk=3 MMAs.
// ============================================================
__device__ __forceinline__ uint32_t smem_u32(const void* p) {
    uint32_t a;
    asm("{ .reg .u64 t; cvta.to.shared.u64 t, %1; cvt.u32.u64 %0, t; }" : "=r"(a) : "l"(p));
    return a;
}
__device__ __forceinline__ void mbar_init(uint32_t addr, uint32_t cnt) {
    asm volatile("mbarrier.init.shared.b64 [%0], %1;" :: "r"(addr), "r"(cnt) : "memory");
}
__device__ __forceinline__ void mbar_expect_tx(uint32_t addr, uint32_t bytes) {
    asm volatile("mbarrier.arrive.expect_tx.shared.b64 _, [%0], %1;"
                 :: "r"(addr), "r"(bytes) : "memory");
}
__device__ __forceinline__ void mbar_arrive(uint32_t addr) {
    asm volatile("mbarrier.arrive.shared.b64 _, [%0];" :: "r"(addr) : "memory");
}
__device__ __forceinline__ void mbar_wait(uint32_t mbar, uint32_t parity) {
    uint32_t done;
    asm volatile("{\n\t.reg .pred p;\n\t"
        "mbarrier.try_wait.parity.acquire.cta.shared::cta.b64 p, [%1], %2;\n\t"
        "selp.b32 %0, 1, 0, p;\n\t}"
        : "=r"(done) : "r"(mbar), "r"(parity) : "memory");
    while (!done) {
        asm volatile("{\n\t.reg .pred p;\n\t"
            "mbarrier.try_wait.parity.acquire.cta.shared::cta.b64 p, [%1], %2, 0x989680;\n\t"
            "selp.b32 %0, 1, 0, p;\n\t}"
            : "=r"(done) : "r"(mbar), "r"(parity) : "memory");
    }
}
__device__ __forceinline__ void bulk_g2s(uint32_t dst, const void* src, uint32_t bytes,
                                         uint32_t mbar) {
    asm volatile(
        "cp.async.bulk.shared::cluster.global.mbarrier::complete_tx::bytes [%0], [%1], %2, [%3];"
        :: "r"(dst), "l"(src), "r"(bytes), "r"(mbar) : "memory");
}
__device__ __forceinline__ void ldmatrix_x4(uint32_t* r, uint32_t addr) {
    asm volatile("ldmatrix.sync.aligned.m8n8.x4.shared.b16 {%0,%1,%2,%3}, [%4];"
                 : "=r"(r[0]), "=r"(r[1]), "=r"(r[2]), "=r"(r[3]) : "r"(addr));
}
__device__ __forceinline__ void mma16816(float* c, const uint32_t* a, uint32_t b0, uint32_t b1) {
    asm volatile(
        "mma.sync.aligned.m16n8k16.row.col.f32.f16.f16.f32 "
        "{%0,%1,%2,%3}, {%4,%5,%6,%7}, {%8,%9}, {%0,%1,%2,%3};"
        : "+f"(c[0]), "+f"(c[1]), "+f"(c[2]), "+f"(c[3])
        : "r"(a[0]), "r"(a[1]), "r"(a[2]), "r"(a[3]), "r"(b0), "r"(b1));
}

__global__ void __launch_bounds__(288, 2) gemm_kernel(
    const float* __restrict__ bias, float* __restrict__ out)
{
    extern __shared__ char smem[];
    const uint32_t raw = smem_u32(smem);
    const uint32_t mbF = raw;             // 3 full barriers (8B each)
    const uint32_t mbE = raw + 24;        // 3 empty barriers
    const uint32_t sb = (raw + 64 + 1023u) & ~1023u;   // 1KB-aligned stage base
    const int tid = threadIdx.x;
    const int wid = tid >> 5;
    const int lane = tid & 31;

    const int nt = blockIdx.x;
    const int mt = blockIdx.y;

    const char* baseA = (const char*)g_Xt + (size_t)mt * NKS * TILE_BYTES;
    const char* baseB = (const char*)g_Wt + (size_t)nt * NKS * TILE_BYTES;

    if (tid == 0) {
        #pragma unroll
        for (int s = 0; s < NSTAGE; s++) {
            mbar_init(mbF + s * 8, 1);     // expect_tx arrive
            mbar_init(mbE + s * 8, 8);     // 8 consumer warps
        }
        asm volatile("fence.proxy.async;" ::: "memory");
    }
    __syncthreads();

    if (wid == 8) {
        // ================= producer warp =================
        if (lane == 0) {
            for (int i = 0; i < NKS; i++) {
                const int st = (i % NSTAGE);
                if (i >= NSTAGE)
                    mbar_wait(mbE + st * 8, (uint32_t)(((i / NSTAGE) - 1) & 1));
                const uint32_t bar = mbF + st * 8;
                mbar_expect_tx(bar, (uint32_t)STAGE_B);
                bulk_g2s(sb + st * STAGE_B, baseA + (size_t)i * TILE_BYTES,
                         (uint32_t)TILE_BYTES, bar);
                bulk_g2s(sb + st * STAGE_B + TILE_BYTES, baseB + (size_t)i * TILE_BYTES,
                         (uint32_t)TILE_BYTES, bar);
            }
        }
        return;
    }

    // ================= consumer warps (0..7) =================
    const int warp_m = (wid >> 2) * 64;   // 2 warps along M
    const int warp_n = (wid & 3) * 32;    // 4 warps along N

    float acc[4][4][4];
    #pragma unroll
    for (int i = 0; i < 4; i++)
        #pragma unroll
        for (int j = 0; j < 4; j++)
            #pragma unroll
            for (int r = 0; r < 4; r++) acc[i][j][r] = 0.f;

    // ldmatrix lane addressing: addr = (stagebase + rb) ^ (kk*32)
    const int lrow = lane & 15;
    const int lhc = lane >> 4;
    const uint32_t lxor = (uint32_t)(((lrow & 7) ^ lhc) * 16);
    uint32_t rbA[4], rbB[2];
    #pragma unroll
    for (int i = 0; i < 4; i++)
        rbA[i] = (uint32_t)((warp_m + i * 16 + lrow) * 128) + lxor;
    #pragma unroll
    for (int j = 0; j < 2; j++)
        rbB[j] = (uint32_t)(TILE_BYTES + (warp_n + j * 16 + lrow) * 128) + lxor;

    uint32_t af[2][4][4], bf[2][2][4];   // double-buffered fragments

    // prologue: wait stage 0, load kk0 frags into buf 0
    mbar_wait(mbF + 0, 0);
    {
        const uint32_t abase = sb;
        #pragma unroll
        for (int i = 0; i < 4; i++) ldmatrix_x4(af[0][i], abase + rbA[i]);
        #pragma unroll
        for (int j = 0; j < 2; j++) ldmatrix_x4(bf[0][j], abase + rbB[j]);
    }

    int stage = 0;
    for (int ks = 0; ks < NKS; ks++) {
        const uint32_t abase = sb + stage * STAGE_B;

        // ---- kk = 0..2: load frags kk+1 (same stage) interleaved with MMAs ----
        #pragma unroll
        for (int kk = 0; kk < 3; kk++) {
            const int mbuf = kk & 1;
            const int lb = (kk + 1) & 1;
            const uint32_t kx = (uint32_t)((kk + 1) * 32);

            ldmatrix_x4(af[lb][0], (abase + rbA[0]) ^ kx);
            mma16816(acc[0][0], af[mbuf][0], bf[mbuf][0][0], bf[mbuf][0][2]);
            mma16816(acc[0][1], af[mbuf][0], bf[mbuf][0][1], bf[mbuf][0][3]);
            ldmatrix_x4(af[lb][1], (abase + rbA[1]) ^ kx);
            mma16816(acc[0][2], af[mbuf][0], bf[mbuf][1][0], bf[mbuf][1][2]);
            mma16816(acc[0][3], af[mbuf][0], bf[mbuf][1][1], bf[mbuf][1][3]);
            ldmatrix_x4(af[lb][2], (abase + rbA[2]) ^ kx);
            mma16816(acc[1][0], af[mbuf][1], bf[mbuf][0][0], bf[mbuf][0][2]);
            mma16816(acc[1][1], af[mbuf][1], bf[mbuf][0][1], bf[mbuf][0][3]);
            ldmatrix_x4(af[lb][3], (abase + rbA[3]) ^ kx);
            mma16816(acc[1][2], af[mbuf][1], bf[mbuf][1][0], bf[mbuf][1][2]);
            mma16816(acc[1][3], af[mbuf][1], bf[mbuf][1][1], bf[mbuf][1][3]);
            ldmatrix_x4(bf[lb][0], (abase + rbB[0]) ^ kx);
            mma16816(acc[2][0], af[mbuf][2], bf[mbuf][0][0], bf[mbuf][0][2]);
            mma16816(acc[2][1], af[mbuf][2], bf[mbuf][0][1], bf[mbuf][0][3]);
            ldmatrix_x4(bf[lb][1], (abase + rbB[1]) ^ kx);
            mma16816(acc[2][2], af[mbuf][2], bf[mbuf][1][0], bf[mbuf][1][2]);
            mma16816(acc[2][3], af[mbuf][2], bf[mbuf][1][1], bf[mbuf][1][3]);
            mma16816(acc[3][0], af[mbuf][3], bf[mbuf][0][0], bf[mbuf][0][2]);
            mma16816(acc[3][1], af[mbuf][3], bf[mbuf][0][1], bf[mbuf][0][3]);
            mma16816(acc[3][2], af[mbuf][3], bf[mbuf][1][0], bf[mbuf][1][2]);
            mma16816(acc[3][3], af[mbuf][3], bf[mbuf][1][1], bf[mbuf][1][3]);
        }

        // ---- kk = 3 (mbuf=1): release stage, prefetch kk0 of next stage ----
        if (lane == 0) mbar_arrive(mbE + stage * 8);   // last read of this stage done
        const int nstage = (stage + 1 == NSTAGE) ? 0 : stage + 1;
        const bool more = (ks + 1 < NKS);
        if (more) {
            mbar_wait(mbF + nstage * 8, (uint32_t)(((ks + 1) / NSTAGE) & 1));
            const uint32_t nbase = sb + nstage * STAGE_B;
            ldmatrix_x4(af[0][0], nbase + rbA[0]);
            mma16816(acc[0][0], af[1][0], bf[1][0][0], bf[1][0][2]);
            mma16816(acc[0][1], af[1][0], bf[1][0][1], bf[1][0][3]);
            ldmatrix_x4(af[0][1], nbase + rbA[1]);
            mma16816(acc[0][2], af[1][0], bf[1][1][0], bf[1][1][2]);
            mma16816(acc[0][3], af[1][0], bf[1][1][1], bf[1][1][3]);
            ldmatrix_x4(af[0][2], nbase + rbA[2]);
            mma16816(acc[1][0], af[1][1], bf[1][0][0], bf[1][0][2]);
            mma16816(acc[1][1], af[1][1], bf[1][0][1], bf[1][0][3]);
            ldmatrix_x4(af[0][3], nbase + rbA[3]);
            mma16816(acc[1][2], af[1][1], bf[1][1][0], bf[1][1][2]);
            mma16816(acc[1][3], af[1][1], bf[1][1][1], bf[1][1][3]);
            ldmatrix_x4(bf[0][0], nbase + rbB[0]);
            mma16816(acc[2][0], af[1][2], bf[1][0][0], bf[1][0][2]);
            mma16816(acc[2][1], af[1][2], bf[1][0][1], bf[1][0][3]);
            ldmatrix_x4(bf[0][1], nbase + rbB[1]);
            mma16816(acc[2][2], af[1][2], bf[1][1][0], bf[1][1][2]);
            mma16816(acc[2][3], af[1][2], bf[1][1][1], bf[1][1][3]);
            mma16816(acc[3][0], af[1][3], bf[1][0][0], bf[1][0][2]);
            mma16816(acc[3][1], af[1][3], bf[1][0][1], bf[1][0][3]);
            mma16816(acc[3][2], af[1][3], bf[1][1][0], bf[1][1][2]);
            mma16816(acc[3][3], af[1][3], bf[1][1][1], bf[1][1][3]);
        } else {
            #pragma unroll
            for (int i = 0; i < 4; i++) {
                mma16816(acc[i][0], af[1][i], bf[1][0][0], bf[1][0][2]);
                mma16816(acc[i][1], af[1][i], bf[1][0][1], bf[1][0][3]);
                mma16816(acc[i][2], af[1][i], bf[1][1][0], bf[1][1][2]);
                mma16816(acc[i][3], af[1][i], bf[1][1][1], bf[1][1][3]);
            }
        }
        stage = nstage;
    }

    // ---------- epilogue: bias + store ----------
    const int qm = lane >> 2;            // 0..7
    const int qn = (lane & 3) * 2;       // 0,2,4,6
    #pragma unroll
    for (int j = 0; j < 4; j++) {
        int n0 = nt * TILE_N + warp_n + j * 8 + qn;
        float2 bv = *reinterpret_cast<const float2*>(bias + n0);
        #pragma unroll
        for (int i = 0; i < 4; i++) {
            int m0 = mt * TILE_M + warp_m + i * 16 + qm;
            float2 v0 = { acc[i][j][0] + bv.x, acc[i][j][1] + bv.y };
            float2 v1 = { acc[i][j][2] + bv.x, acc[i][j][3] + bv.y };
            *reinterpret_cast<float2*>(out + (size_t)m0 * NDIM + n0) = v0;
            *reinterpret_cast<float2*>(out + (size_t)(m0 + 8) * NDIM + n0) = v1;
        }
    }
}

// ============================================================
// Launch
// ============================================================
extern "C" void kernel_launch(void* const* d_in, const int* in_sizes, int n_in,
                              void* d_out, int out_size) {
    const float* x     = (const float*)d_in[0];
    const int*   wq    = (const int*)d_in[1];
    const float* scale = (const float*)d_in[2];
    const float* zp    = (const float*)d_in[3];
    const float* bias  = (const float*)d_in[4];
    float* out = (float*)d_out;

    convert_kernel<<<W_BLOCKS + X_BLOCKS, 256>>>(wq, scale, zp, x);

    static bool attr_set = false;
    if (!attr_set) {
        cudaFuncSetAttribute(gemm_kernel, cudaFuncAttributeMaxDynamicSharedMemorySize, SMEM_BYTES);
        attr_set = true;
    }
    dim3 grid(NDIM / TILE_N, MDIM / TILE_M);   // (32, 64)
    gemm_kernel<<<grid, 288, SMEM_BYTES>>>(bias, out);
}

// round 12
// speedup vs baseline: 2.6662x; 2.6662x over previous
#include <cuda_runtime.h>
#include <cuda_fp16.h>
#include <cstdint>

// ============================================================
// Problem dims (fixed)
// ============================================================
#define MDIM 8192     // B*S
#define NDIM 4096
#define KDIM 4096
#define NGROUPS 64    // group size 64

constexpr int TILE_M = 128;
constexpr int TILE_N = 128;
constexpr int KS = 64;                     // halves per K-stage (128 B rows)
constexpr int NKS = KDIM / KS;             // 64
constexpr int TILE_BYTES = TILE_M * 128;   // 16 KB per operand tile-stage
constexpr int NSTAGE = 3;
constexpr int STAGE_B = 2 * TILE_BYTES;    // 32 KB
constexpr int SMEM_BYTES = 2048 + NSTAGE * STAGE_B;   // pad for 1KB align + mbars

// Scratch: half tiles pre-laid-out in GEMM's per-stage swizzled format.
__device__ __half g_Wt[(size_t)NDIM * KDIM];   // 32 MB, tiles (nt*NKS + ks)
__device__ __half g_Xt[(size_t)MDIM * KDIM];   // 64 MB, tiles (mt*NKS + ks)

// ============================================================
// Pass 1 (merged): dequant W and convert X into tiled+swizzled layout.
// ============================================================
constexpr int W_BLOCKS = (int)((size_t)NDIM * KDIM * 2 / 16 / 256);   // 8192
constexpr int X_BLOCKS = (int)((size_t)MDIM * KDIM * 2 / 16 / 256);   // 32768

__global__ void __launch_bounds__(256) convert_kernel(
    const int* __restrict__ q, const float* __restrict__ scale, const float* __restrict__ zp,
    const float* __restrict__ x)
{
    if (blockIdx.x < W_BLOCKS) {
        int t = blockIdx.x * 256 + threadIdx.x;     // target 16B chunk index
        int idx = t & 1023;                         // chunk within 16KB tile
        int tile = t >> 10;                         // nt*NKS + ks
        int ks = tile & (NKS - 1);
        int nt = tile >> 6;
        int r = idx >> 3;
        int cS = idx & 7;
        int c = cS ^ (r & 7);                       // un-swizzled chunk
        int n = nt * 128 + r;
        int k = ks * KS + c * 8;
        const int4* qp = reinterpret_cast<const int4*>(q + (size_t)n * KDIM + k);
        int4 q0 = qp[0], q1 = qp[1];
        float s = scale[n * NGROUPS + ks];          // group == ks (G == KS == 64)
        float z = zp[n * NGROUPS + ks];
        __half2 h[4];
        h[0] = __floats2half2_rn(((float)q0.x - z) * s, ((float)q0.y - z) * s);
        h[1] = __floats2half2_rn(((float)q0.z - z) * s, ((float)q0.w - z) * s);
        h[2] = __floats2half2_rn(((float)q1.x - z) * s, ((float)q1.y - z) * s);
        h[3] = __floats2half2_rn(((float)q1.z - z) * s, ((float)q1.w - z) * s);
        reinterpret_cast<uint4*>(g_Wt)[t] = *reinterpret_cast<uint4*>(h);
    } else {
        int t = (blockIdx.x - W_BLOCKS) * 256 + threadIdx.x;
        int idx = t & 1023;
        int tile = t >> 10;                         // mt*NKS + ks
        int ks = tile & (NKS - 1);
        int mt = tile >> 6;
        int r = idx >> 3;
        int cS = idx & 7;
        int c = cS ^ (r & 7);
        int m = mt * 128 + r;
        int k = ks * KS + c * 8;
        const float4* xp = reinterpret_cast<const float4*>(x + (size_t)m * KDIM + k);
        float4 a = xp[0], b = xp[1];
        __half2 h[4];
        h[0] = __floats2half2_rn(a.x, a.y);
        h[1] = __floats2half2_rn(a.z, a.w);
        h[2] = __floats2half2_rn(b.x, b.y);
        h[3] = __floats2half2_rn(b.z, b.w);
        reinterpret_cast<uint4*>(g_Xt)[t] = *reinterpret_cast<uint4*>(h);
    }
}

// ============================================================
// Pass 2: GEMM  out[M,N] = X @ W^T + bias   (fp16 in, fp32 acc)
// CTA 128x128, 8 warps (warp 64x32), 3-stage ring, 2 CTAs/SM.
// R10 dataflow, but stage-top __syncthreads replaced by per-stage empty
// mbarriers (8 warp arrivals at kk=3 entry). Producer = tid0 inline; it
// waits empty(slot) before re-issuing the 2 x 16KB cp.async.bulk.
// Full-wait stays at stage TOP (a whole stage of copy slack, as in R10).
// ============================================================
__device__ __forceinline__ uint32_t smem_u32(const void* p) {
    uint32_t a;
    asm("{ .reg .u64 t; cvta.to.shared.u64 t, %1; cvt.u32.u64 %0, t; }" : "=r"(a) : "l"(p));
    return a;
}
__device__ __forceinline__ void mbar_init(uint32_t addr, uint32_t cnt) {
    asm volatile("mbarrier.init.shared.b64 [%0], %1;" :: "r"(addr), "r"(cnt) : "memory");
}
__device__ __forceinline__ void mbar_expect_tx(uint32_t addr, uint32_t bytes) {
    asm volatile("mbarrier.arrive.expect_tx.shared.b64 _, [%0], %1;"
                 :: "r"(addr), "r"(bytes) : "memory");
}
__device__ __forceinline__ void mbar_arrive(uint32_t addr) {
    asm volatile("mbarrier.arrive.release.cta.shared::cta.b64 _, [%0];"
                 :: "r"(addr) : "memory");
}
__device__ __forceinline__ void mbar_wait(uint32_t mbar, uint32_t parity) {
    uint32_t done;
    asm volatile("{\n\t.reg .pred p;\n\t"
        "mbarrier.try_wait.parity.acquire.cta.shared::cta.b64 p, [%1], %2;\n\t"
        "selp.b32 %0, 1, 0, p;\n\t}"
        : "=r"(done) : "r"(mbar), "r"(parity) : "memory");
    while (!done) {
        asm volatile("{\n\t.reg .pred p;\n\t"
            "mbarrier.try_wait.parity.acquire.cta.shared::cta.b64 p, [%1], %2, 0x989680;\n\t"
            "selp.b32 %0, 1, 0, p;\n\t}"
            : "=r"(done) : "r"(mbar), "r"(parity) : "memory");
    }
}
__device__ __forceinline__ void bulk_g2s(uint32_t dst, const void* src, uint32_t bytes,
                                         uint32_t mbar) {
    asm volatile(
        "cp.async.bulk.shared::cluster.global.mbarrier::complete_tx::bytes [%0], [%1], %2, [%3];"
        :: "r"(dst), "l"(src), "r"(bytes), "r"(mbar) : "memory");
}
__device__ __forceinline__ void ldmatrix_x4(uint32_t* r, uint32_t addr) {
    asm volatile("ldmatrix.sync.aligned.m8n8.x4.shared.b16 {%0,%1,%2,%3}, [%4];"
                 : "=r"(r[0]), "=r"(r[1]), "=r"(r[2]), "=r"(r[3]) : "r"(addr));
}
__device__ __forceinline__ void mma16816(float* c, const uint32_t* a, uint32_t b0, uint32_t b1) {
    asm volatile(
        "mma.sync.aligned.m16n8k16.row.col.f32.f16.f16.f32 "
        "{%0,%1,%2,%3}, {%4,%5,%6,%7}, {%8,%9}, {%0,%1,%2,%3};"
        : "+f"(c[0]), "+f"(c[1]), "+f"(c[2]), "+f"(c[3])
        : "r"(a[0]), "r"(a[1]), "r"(a[2]), "r"(a[3]), "r"(b0), "r"(b1));
}

__global__ void __launch_bounds__(256, 2) gemm_kernel(
    const float* __restrict__ bias, float* __restrict__ out)
{
    extern __shared__ char smem[];
    const uint32_t raw = smem_u32(smem);
    const uint32_t mbF = raw;             // 3 full barriers (8B each)
    const uint32_t mbE = raw + 24;        // 3 empty barriers
    const uint32_t sb = (raw + 64 + 1023u) & ~1023u;   // 1KB-aligned stage base
    const int tid = threadIdx.x;
    const int wid = tid >> 5;
    const int lane = tid & 31;

    const int nt = blockIdx.x;
    const int mt = blockIdx.y;
    const int warp_m = (wid >> 2) * 64;   // 2 warps along M
    const int warp_n = (wid & 3) * 32;    // 4 warps along N

    const char* baseA = (const char*)g_Xt + (size_t)mt * NKS * TILE_BYTES;
    const char* baseB = (const char*)g_Wt + (size_t)nt * NKS * TILE_BYTES;

    if (tid == 0) {
        #pragma unroll
        for (int s = 0; s < NSTAGE; s++) {
            mbar_init(mbF + s * 8, 1);     // completed by expect_tx transactions
            mbar_init(mbE + s * 8, 8);     // 8 consumer-warp arrivals
        }
        asm volatile("fence.proxy.async;" ::: "memory");
    }
    __syncthreads();   // once, before any bulk/wait

    auto issue = [&](int i, int st) {
        const uint32_t bar = mbF + st * 8;
        mbar_expect_tx(bar, (uint32_t)STAGE_B);
        bulk_g2s(sb + st * STAGE_B, baseA + (size_t)i * TILE_BYTES,
                 (uint32_t)TILE_BYTES, bar);
        bulk_g2s(sb + st * STAGE_B + TILE_BYTES, baseB + (size_t)i * TILE_BYTES,
                 (uint32_t)TILE_BYTES, bar);
    };

    if (tid == 0) { issue(0, 0); issue(1, 1); }

    float acc[4][4][4];
    #pragma unroll
    for (int i = 0; i < 4; i++)
        #pragma unroll
        for (int j = 0; j < 4; j++)
            #pragma unroll
            for (int r = 0; r < 4; r++) acc[i][j][r] = 0.f;

    // ldmatrix lane addressing: addr = (stagebase + rb) ^ (kk*32)
    const int lrow = lane & 15;
    const int lhc = lane >> 4;
    const uint32_t lxor = (uint32_t)(((lrow & 7) ^ lhc) * 16);
    uint32_t rbA[4], rbB[2];
    #pragma unroll
    for (int i = 0; i < 4; i++)
        rbA[i] = (uint32_t)((warp_m + i * 16 + lrow) * 128) + lxor;
    #pragma unroll
    for (int j = 0; j < 2; j++)
        rbB[j] = (uint32_t)(TILE_BYTES + (warp_n + j * 16 + lrow) * 128) + lxor;

    uint32_t af[2][4][4], bf[2][2][4];   // double-buffered fragments

    int stage = 0, phase = 0;
    for (int ks = 0; ks < NKS; ks++) {
        // per-warp wait for this stage's data (full stage of slack for the copy)
        mbar_wait(mbF + stage * 8, (uint32_t)phase);

        // producer: re-issue into slot (stage+2)%3 once its previous occupant
        // (tile ks-1) has been released by all 8 warps.
        if (tid == 0 && ks + 2 < NKS) {
            const int st2 = (stage + 2 >= NSTAGE) ? stage + 2 - NSTAGE : stage + 2;
            if (ks >= 1) mbar_wait(mbE + st2 * 8, (uint32_t)((((ks + 2) / NSTAGE) - 1) & 1));
            issue(ks + 2, st2);
        }

        const uint32_t abase = sb + stage * STAGE_B;

        // kk=0 fragment burst (buf 0)
        #pragma unroll
        for (int i = 0; i < 4; i++) ldmatrix_x4(af[0][i], abase + rbA[i]);
        #pragma unroll
        for (int j = 0; j < 2; j++) ldmatrix_x4(bf[0][j], abase + rbB[j]);

        #pragma unroll
        for (int kk = 0; kk < 4; kk++) {
            const int mbuf = kk & 1;
            const int lb = (kk + 1) & 1;
            const bool dl = (kk < 3);
            const uint32_t kx = (uint32_t)((kk + 1) * 32);

            // last smem reads of this stage happen at kk=2; release at kk=3 entry
            if (kk == 3 && lane == 0) mbar_arrive(mbE + stage * 8);

            // interleaved: 6 LDSM(kk+1) spread between MMA pairs
            if (dl) ldmatrix_x4(af[lb][0], (abase + rbA[0]) ^ kx);
            mma16816(acc[0][0], af[mbuf][0], bf[mbuf][0][0], bf[mbuf][0][2]);
            mma16816(acc[0][1], af[mbuf][0], bf[mbuf][0][1], bf[mbuf][0][3]);
            if (dl) ldmatrix_x4(af[lb][1], (abase + rbA[1]) ^ kx);
            mma16816(acc[0][2], af[mbuf][0], bf[mbuf][1][0], bf[mbuf][1][2]);
            mma16816(acc[0][3], af[mbuf][0], bf[mbuf][1][1], bf[mbuf][1][3]);
            if (dl) ldmatrix_x4(af[lb][2], (abase + rbA[2]) ^ kx);
            mma16816(acc[1][0], af[mbuf][1], bf[mbuf][0][0], bf[mbuf][0][2]);
            mma16816(acc[1][1], af[mbuf][1], bf[mbuf][0][1], bf[mbuf][0][3]);
            if (dl) ldmatrix_x4(af[lb][3], (abase + rbA[3]) ^ kx);
            mma16816(acc[1][2], af[mbuf][1], bf[mbuf][1][0], bf[mbuf][1][2]);
            mma16816(acc[1][3], af[mbuf][1], bf[mbuf][1][1], bf[mbuf][1][3]);
            if (dl) ldmatrix_x4(bf[lb][0], (abase + rbB[0]) ^ kx);
            mma16816(acc[2][0], af[mbuf][2], bf[mbuf][0][0], bf[mbuf][0][2]);
            mma16816(acc[2][1], af[mbuf][2], bf[mbuf][0][1], bf[mbuf][0][3]);
            if (dl) ldmatrix_x4(bf[lb][1], (abase + rbB[1]) ^ kx);
            mma16816(acc[2][2], af[mbuf][2], bf[mbuf][1][0], bf[mbuf][1][2]);
            mma16816(acc[2][3], af[mbuf][2], bf[mbuf][1][1], bf[mbuf][1][3]);
            mma16816(acc[3][0], af[mbuf][3], bf[mbuf][0][0], bf[mbuf][0][2]);
            mma16816(acc[3][1], af[mbuf][3], bf[mbuf][0][1], bf[mbuf][0][3]);
            mma16816(acc[3][2], af[mbuf][3], bf[mbuf][1][0], bf[mbuf][1][2]);
            mma16816(acc[3][3], af[mbuf][3], bf[mbuf][1][1], bf[mbuf][1][3]);
        }
        if (++stage == NSTAGE) { stage = 0; phase ^= 1; }
    }

    // ---------- epilogue: bias + store ----------
    const int qm = lane >> 2;            // 0..7
    const int qn = (lane & 3) * 2;       // 0,2,4,6
    #pragma unroll
    for (int j = 0; j < 4; j++) {
        int n0 = nt * TILE_N + warp_n + j * 8 + qn;
        float2 bv = *reinterpret_cast<const float2*>(bias + n0);
        #pragma unroll
        for (int i = 0; i < 4; i++) {
            int m0 = mt * TILE_M + warp_m + i * 16 + qm;
            float2 v0 = { acc[i][j][0] + bv.x, acc[i][j][1] + bv.y };
            float2 v1 = { acc[i][j][2] + bv.x, acc[i][j][3] + bv.y };
            *reinterpret_cast<float2*>(out + (size_t)m0 * NDIM + n0) = v0;
            *reinterpret_cast<float2*>(out + (size_t)(m0 + 8) * NDIM + n0) = v1;
        }
    }
}

// ============================================================
// Launch
// ============================================================
extern "C" void kernel_launch(void* const* d_in, const int* in_sizes, int n_in,
                              void* d_out, int out_size) {
    const float* x     = (const float*)d_in[0];
    const int*   wq    = (const int*)d_in[1];
    const float* scale = (const float*)d_in[2];
    const float* zp    = (const float*)d_in[3];
    const float* bias  = (const float*)d_in[4];
    float* out = (float*)d_out;

    convert_kernel<<<W_BLOCKS + X_BLOCKS, 256>>>(wq, scale, zp, x);

    static bool attr_set = false;
    if (!attr_set) {
        cudaFuncSetAttribute(gemm_kernel, cudaFuncAttributeMaxDynamicSharedMemorySize, SMEM_BYTES);
        attr_set = true;
    }
    dim3 grid(NDIM / TILE_N, MDIM / TILE_M);   // (32, 64)
    gemm_kernel<<<grid, 256, SMEM_BYTES>>>(bias, out);
}

// round 13
// speedup vs baseline: 3.2081x; 1.2032x over previous
#include <cuda_runtime.h>
#include <cuda_fp16.h>
#include <cstdint>

// ============================================================
// Problem dims (fixed)
// ============================================================
#define MDIM 8192     // B*S
#define NDIM 4096
#define KDIM 4096
#define NGROUPS 64    // group size 64

constexpr int TILE_M = 128;
constexpr int TILE_N = 128;
constexpr int KS = 64;                     // halves per K-stage (128 B rows)
constexpr int NKS = KDIM / KS;             // 64
constexpr int TILE_BYTES = TILE_M * 128;   // 16 KB per operand tile-stage
constexpr int NSTAGE = 3;
constexpr int STAGE_B = 2 * TILE_BYTES;    // 32 KB
constexpr int SMEM_BYTES = 2048 + NSTAGE * STAGE_B;   // pad for 1KB align + mbars

// Scratch: half tiles pre-laid-out in GEMM's per-stage swizzled format.
__device__ __half g_Wt[(size_t)NDIM * KDIM];   // 32 MB, tiles (nt*NKS + ks)
__device__ __half g_Xt[(size_t)MDIM * KDIM];   // 64 MB, tiles (mt*NKS + ks)

// ============================================================
// Pass 1 (merged): dequant W and convert X into tiled+swizzled layout.
// ============================================================
constexpr int W_BLOCKS = (int)((size_t)NDIM * KDIM * 2 / 16 / 256);   // 8192
constexpr int X_BLOCKS = (int)((size_t)MDIM * KDIM * 2 / 16 / 256);   // 32768

__global__ void __launch_bounds__(256) convert_kernel(
    const int* __restrict__ q, const float* __restrict__ scale, const float* __restrict__ zp,
    const float* __restrict__ x)
{
    if (blockIdx.x < W_BLOCKS) {
        int t = blockIdx.x * 256 + threadIdx.x;     // target 16B chunk index
        int idx = t & 1023;                         // chunk within 16KB tile
        int tile = t >> 10;                         // nt*NKS + ks
        int ks = tile & (NKS - 1);
        int nt = tile >> 6;
        int r = idx >> 3;
        int cS = idx & 7;
        int c = cS ^ (r & 7);                       // un-swizzled chunk
        int n = nt * 128 + r;
        int k = ks * KS + c * 8;
        const int4* qp = reinterpret_cast<const int4*>(q + (size_t)n * KDIM + k);
        int4 q0 = qp[0], q1 = qp[1];
        float s = scale[n * NGROUPS + ks];          // group == ks (G == KS == 64)
        float z = zp[n * NGROUPS + ks];
        __half2 h[4];
        h[0] = __floats2half2_rn(((float)q0.x - z) * s, ((float)q0.y - z) * s);
        h[1] = __floats2half2_rn(((float)q0.z - z) * s, ((float)q0.w - z) * s);
        h[2] = __floats2half2_rn(((float)q1.x - z) * s, ((float)q1.y - z) * s);
        h[3] = __floats2half2_rn(((float)q1.z - z) * s, ((float)q1.w - z) * s);
        reinterpret_cast<uint4*>(g_Wt)[t] = *reinterpret_cast<uint4*>(h);
    } else {
        int t = (blockIdx.x - W_BLOCKS) * 256 + threadIdx.x;
        int idx = t & 1023;
        int tile = t >> 10;                         // mt*NKS + ks
        int ks = tile & (NKS - 1);
        int mt = tile >> 6;
        int r = idx >> 3;
        int cS = idx & 7;
        int c = cS ^ (r & 7);
        int m = mt * 128 + r;
        int k = ks * KS + c * 8;
        const float4* xp = reinterpret_cast<const float4*>(x + (size_t)m * KDIM + k);
        float4 a = xp[0], b = xp[1];
        __half2 h[4];
        h[0] = __floats2half2_rn(a.x, a.y);
        h[1] = __floats2half2_rn(a.z, a.w);
        h[2] = __floats2half2_rn(b.x, b.y);
        h[3] = __floats2half2_rn(b.z, b.w);
        reinterpret_cast<uint4*>(g_Xt)[t] = *reinterpret_cast<uint4*>(h);
    }
}

// ============================================================
// Pass 2: GEMM  out[M,N] = X @ W^T + bias   (fp16 in, fp32 acc)
// CTA 128x128, 8 warps (warp 64x32), 3-stage ring, 2 CTAs/SM.
// R12 structure + CROSS-STAGE FRAGMENT PREFETCH: the full-wait for stage
// s+1 sits in the middle of kk=3 of stage s (after 8 register-resident
// MMAs), and the kk0 LDSMs of s+1 interleave with the last 8 MMAs of s.
// Steady-state stages start with MMAs immediately -> no head-of-stage
// dependent-load stall.
// ============================================================
__device__ __forceinline__ uint32_t smem_u32(const void* p) {
    uint32_t a;
    asm("{ .reg .u64 t; cvta.to.shared.u64 t, %1; cvt.u32.u64 %0, t; }" : "=r"(a) : "l"(p));
    return a;
}
__device__ __forceinline__ void mbar_init(uint32_t addr, uint32_t cnt) {
    asm volatile("mbarrier.init.shared.b64 [%0], %1;" :: "r"(addr), "r"(cnt) : "memory");
}
__device__ __forceinline__ void mbar_expect_tx(uint32_t addr, uint32_t bytes) {
    asm volatile("mbarrier.arrive.expect_tx.shared.b64 _, [%0], %1;"
                 :: "r"(addr), "r"(bytes) : "memory");
}
__device__ __forceinline__ void mbar_arrive(uint32_t addr) {
    asm volatile("mbarrier.arrive.release.cta.shared::cta.b64 _, [%0];"
                 :: "r"(addr) : "memory");
}
__device__ __forceinline__ void mbar_wait(uint32_t mbar, uint32_t parity) {
    uint32_t done;
    asm volatile("{\n\t.reg .pred p;\n\t"
        "mbarrier.try_wait.parity.acquire.cta.shared::cta.b64 p, [%1], %2;\n\t"
        "selp.b32 %0, 1, 0, p;\n\t}"
        : "=r"(done) : "r"(mbar), "r"(parity) : "memory");
    while (!done) {
        asm volatile("{\n\t.reg .pred p;\n\t"
            "mbarrier.try_wait.parity.acquire.cta.shared::cta.b64 p, [%1], %2, 0x989680;\n\t"
            "selp.b32 %0, 1, 0, p;\n\t}"
            : "=r"(done) : "r"(mbar), "r"(parity) : "memory");
    }
}
__device__ __forceinline__ void bulk_g2s(uint32_t dst, const void* src, uint32_t bytes,
                                         uint32_t mbar) {
    asm volatile(
        "cp.async.bulk.shared::cluster.global.mbarrier::complete_tx::bytes [%0], [%1], %2, [%3];"
        :: "r"(dst), "l"(src), "r"(bytes), "r"(mbar) : "memory");
}
__device__ __forceinline__ void ldmatrix_x4(uint32_t* r, uint32_t addr) {
    asm volatile("ldmatrix.sync.aligned.m8n8.x4.shared.b16 {%0,%1,%2,%3}, [%4];"
                 : "=r"(r[0]), "=r"(r[1]), "=r"(r[2]), "=r"(r[3]) : "r"(addr));
}
__device__ __forceinline__ void mma16816(float* c, const uint32_t* a, uint32_t b0, uint32_t b1) {
    asm volatile(
        "mma.sync.aligned.m16n8k16.row.col.f32.f16.f16.f32 "
        "{%0,%1,%2,%3}, {%4,%5,%6,%7}, {%8,%9}, {%0,%1,%2,%3};"
        : "+f"(c[0]), "+f"(c[1]), "+f"(c[2]), "+f"(c[3])
        : "r"(a[0]), "r"(a[1]), "r"(a[2]), "r"(a[3]), "r"(b0), "r"(b1));
}

__global__ void __launch_bounds__(256, 2) gemm_kernel(
    const float* __restrict__ bias, float* __restrict__ out)
{
    extern __shared__ char smem[];
    const uint32_t raw = smem_u32(smem);
    const uint32_t mbF = raw;             // 3 full barriers (8B each)
    const uint32_t mbE = raw + 24;        // 3 empty barriers
    const uint32_t sb = (raw + 64 + 1023u) & ~1023u;   // 1KB-aligned stage base
    const int tid = threadIdx.x;
    const int wid = tid >> 5;
    const int lane = tid & 31;

    const int nt = blockIdx.x;
    const int mt = blockIdx.y;
    const int warp_m = (wid >> 2) * 64;   // 2 warps along M
    const int warp_n = (wid & 3) * 32;    // 4 warps along N

    const char* baseA = (const char*)g_Xt + (size_t)mt * NKS * TILE_BYTES;
    const char* baseB = (const char*)g_Wt + (size_t)nt * NKS * TILE_BYTES;

    if (tid == 0) {
        #pragma unroll
        for (int s = 0; s < NSTAGE; s++) {
            mbar_init(mbF + s * 8, 1);     // completed by expect_tx transactions
            mbar_init(mbE + s * 8, 8);     // 8 consumer-warp arrivals
        }
        asm volatile("fence.proxy.async;" ::: "memory");
    }
    __syncthreads();   // once, before any bulk/wait

    auto issue = [&](int i, int st) {
        const uint32_t bar = mbF + st * 8;
        mbar_expect_tx(bar, (uint32_t)STAGE_B);
        bulk_g2s(sb + st * STAGE_B, baseA + (size_t)i * TILE_BYTES,
                 (uint32_t)TILE_BYTES, bar);
        bulk_g2s(sb + st * STAGE_B + TILE_BYTES, baseB + (size_t)i * TILE_BYTES,
                 (uint32_t)TILE_BYTES, bar);
    };

    if (tid == 0) { issue(0, 0); issue(1, 1); }

    float acc[4][4][4];
    #pragma unroll
    for (int i = 0; i < 4; i++)
        #pragma unroll
        for (int j = 0; j < 4; j++)
            #pragma unroll
            for (int r = 0; r < 4; r++) acc[i][j][r] = 0.f;

    // ldmatrix lane addressing: addr = (stagebase + rb) ^ (kk*32)
    const int lrow = lane & 15;
    const int lhc = lane >> 4;
    const uint32_t lxor = (uint32_t)(((lrow & 7) ^ lhc) * 16);
    uint32_t rbA[4], rbB[2];
    #pragma unroll
    for (int i = 0; i < 4; i++)
        rbA[i] = (uint32_t)((warp_m + i * 16 + lrow) * 128) + lxor;
    #pragma unroll
    for (int j = 0; j < 2; j++)
        rbB[j] = (uint32_t)(TILE_BYTES + (warp_n + j * 16 + lrow) * 128) + lxor;

    uint32_t af[2][4][4], bf[2][2][4];   // double-buffered fragments

    // prologue: wait tile 0, load its kk0 fragments into buf 0
    mbar_wait(mbF + 0, 0);
    #pragma unroll
    for (int i = 0; i < 4; i++) ldmatrix_x4(af[0][i], sb + rbA[i]);
    #pragma unroll
    for (int j = 0; j < 2; j++) ldmatrix_x4(bf[0][j], sb + rbB[j]);

    int stage = 0;
    for (int ks = 0; ks < NKS; ks++) {
        // producer: re-issue into slot (stage+2)%3 once released by all 8 warps
        if (tid == 0 && ks + 2 < NKS) {
            const int st2 = (stage + 2 >= NSTAGE) ? stage + 2 - NSTAGE : stage + 2;
            if (ks >= 1) mbar_wait(mbE + st2 * 8, (uint32_t)((((ks + 2) / NSTAGE) - 1) & 1));
            issue(ks + 2, st2);
        }

        const uint32_t abase = sb + stage * STAGE_B;

        // ---- kk = 0..2: MMAs on buf(kk&1), LDSM kk+1 (same stage) interleaved ----
        #pragma unroll
        for (int kk = 0; kk < 3; kk++) {
            const int mbuf = kk & 1;
            const int lb = (kk + 1) & 1;
            const uint32_t kx = (uint32_t)((kk + 1) * 32);

            ldmatrix_x4(af[lb][0], (abase + rbA[0]) ^ kx);
            mma16816(acc[0][0], af[mbuf][0], bf[mbuf][0][0], bf[mbuf][0][2]);
            mma16816(acc[0][1], af[mbuf][0], bf[mbuf][0][1], bf[mbuf][0][3]);
            ldmatrix_x4(af[lb][1], (abase + rbA[1]) ^ kx);
            mma16816(acc[0][2], af[mbuf][0], bf[mbuf][1][0], bf[mbuf][1][2]);
            mma16816(acc[0][3], af[mbuf][0], bf[mbuf][1][1], bf[mbuf][1][3]);
            ldmatrix_x4(af[lb][2], (abase + rbA[2]) ^ kx);
            mma16816(acc[1][0], af[mbuf][1], bf[mbuf][0][0], bf[mbuf][0][2]);
            mma16816(acc[1][1], af[mbuf][1], bf[mbuf][0][1], bf[mbuf][0][3]);
            ldmatrix_x4(af[lb][3], (abase + rbA[3]) ^ kx);
            mma16816(acc[1][2], af[mbuf][1], bf[mbuf][1][0], bf[mbuf][1][2]);
            mma16816(acc[1][3], af[mbuf][1], bf[mbuf][1][1], bf[mbuf][1][3]);
            ldmatrix_x4(bf[lb][0], (abase + rbB[0]) ^ kx);
            mma16816(acc[2][0], af[mbuf][2], bf[mbuf][0][0], bf[mbuf][0][2]);
            mma16816(acc[2][1], af[mbuf][2], bf[mbuf][0][1], bf[mbuf][0][3]);
            ldmatrix_x4(bf[lb][1], (abase + rbB[1]) ^ kx);
            mma16816(acc[2][2], af[mbuf][2], bf[mbuf][1][0], bf[mbuf][1][2]);
            mma16816(acc[2][3], af[mbuf][2], bf[mbuf][1][1], bf[mbuf][1][3]);
            mma16816(acc[3][0], af[mbuf][3], bf[mbuf][0][0], bf[mbuf][0][2]);
            mma16816(acc[3][1], af[mbuf][3], bf[mbuf][0][1], bf[mbuf][0][3]);
            mma16816(acc[3][2], af[mbuf][3], bf[mbuf][1][0], bf[mbuf][1][2]);
            mma16816(acc[3][3], af[mbuf][3], bf[mbuf][1][1], bf[mbuf][1][3]);
        }

        // ---- kk = 3 (buf 1, all fragments register-resident) ----
        if (lane == 0) mbar_arrive(mbE + stage * 8);   // release this stage early

        // first 8 MMAs: no smem dependence
        mma16816(acc[0][0], af[1][0], bf[1][0][0], bf[1][0][2]);
        mma16816(acc[0][1], af[1][0], bf[1][0][1], bf[1][0][3]);
        mma16816(acc[0][2], af[1][0], bf[1][1][0], bf[1][1][2]);
        mma16816(acc[0][3], af[1][0], bf[1][1][1], bf[1][1][3]);
        mma16816(acc[1][0], af[1][1], bf[1][0][0], bf[1][0][2]);
        mma16816(acc[1][1], af[1][1], bf[1][0][1], bf[1][0][3]);
        mma16816(acc[1][2], af[1][1], bf[1][1][0], bf[1][1][2]);
        mma16816(acc[1][3], af[1][1], bf[1][1][1], bf[1][1][3]);

        const int nstage = (stage + 1 == NSTAGE) ? 0 : stage + 1;
        if (ks + 1 < NKS) {
            // wait for next tile (issued 2 stages ago -> usually fast-path),
            // then prefetch its kk0 fragments interleaved with the last 8 MMAs
            mbar_wait(mbF + nstage * 8, (uint32_t)(((ks + 1) / NSTAGE) & 1));
            const uint32_t nbase = sb + nstage * STAGE_B;
            ldmatrix_x4(af[0][0], nbase + rbA[0]);
            mma16816(acc[2][0], af[1][2], bf[1][0][0], bf[1][0][2]);
            mma16816(acc[2][1], af[1][2], bf[1][0][1], bf[1][0][3]);
            ldmatrix_x4(af[0][1], nbase + rbA[1]);
            mma16816(acc[2][2], af[1][2], bf[1][1][0], bf[1][1][2]);
            mma16816(acc[2][3], af[1][2], bf[1][1][1], bf[1][1][3]);
            ldmatrix_x4(af[0][2], nbase + rbA[2]);
            mma16816(acc[3][0], af[1][3], bf[1][0][0], bf[1][0][2]);
            mma16816(acc[3][1], af[1][3], bf[1][0][1], bf[1][0][3]);
            ldmatrix_x4(af[0][3], nbase + rbA[3]);
            mma16816(acc[3][2], af[1][3], bf[1][1][0], bf[1][1][2]);
            ldmatrix_x4(bf[0][0], nbase + rbB[0]);
            mma16816(acc[3][3], af[1][3], bf[1][1][1], bf[1][1][3]);
            ldmatrix_x4(bf[0][1], nbase + rbB[1]);
        } else {
            mma16816(acc[2][0], af[1][2], bf[1][0][0], bf[1][0][2]);
            mma16816(acc[2][1], af[1][2], bf[1][0][1], bf[1][0][3]);
            mma16816(acc[2][2], af[1][2], bf[1][1][0], bf[1][1][2]);
            mma16816(acc[2][3], af[1][2], bf[1][1][1], bf[1][1][3]);
            mma16816(acc[3][0], af[1][3], bf[1][0][0], bf[1][0][2]);
            mma16816(acc[3][1], af[1][3], bf[1][0][1], bf[1][0][3]);
            mma16816(acc[3][2], af[1][3], bf[1][1][0], bf[1][1][2]);
            mma16816(acc[3][3], af[1][3], bf[1][1][1], bf[1][1][3]);
        }
        stage = nstage;
    }

    // ---------- epilogue: bias + store ----------
    const int qm = lane >> 2;            // 0..7
    const int qn = (lane & 3) * 2;       // 0,2,4,6
    #pragma unroll
    for (int j = 0; j < 4; j++) {
        int n0 = nt * TILE_N + warp_n + j * 8 + qn;
        float2 bv = *reinterpret_cast<const float2*>(bias + n0);
        #pragma unroll
        for (int i = 0; i < 4; i++) {
            int m0 = mt * TILE_M + warp_m + i * 16 + qm;
            float2 v0 = { acc[i][j][0] + bv.x, acc[i][j][1] + bv.y };
            float2 v1 = { acc[i][j][2] + bv.x, acc[i][j][3] + bv.y };
            *reinterpret_cast<float2*>(out + (size_t)m0 * NDIM + n0) = v0;
            *reinterpret_cast<float2*>(out + (size_t)(m0 + 8) * NDIM + n0) = v1;
        }
    }
}

// ============================================================
// Launch
// ============================================================
extern "C" void kernel_launch(void* const* d_in, const int* in_sizes, int n_in,
                              void* d_out, int out_size) {
    const float* x     = (const float*)d_in[0];
    const int*   wq    = (const int*)d_in[1];
    const float* scale = (const float*)d_in[2];
    const float* zp    = (const float*)d_in[3];
    const float* bias  = (const float*)d_in[4];
    float* out = (float*)d_out;

    convert_kernel<<<W_BLOCKS + X_BLOCKS, 256>>>(wq, scale, zp, x);

    static bool attr_set = false;
    if (!attr_set) {
        cudaFuncSetAttribute(gemm_kernel, cudaFuncAttributeMaxDynamicSharedMemorySize, SMEM_BYTES);
        attr_set = true;
    }
    dim3 grid(NDIM / TILE_N, MDIM / TILE_M);   // (32, 64)
    gemm_kernel<<<grid, 256, SMEM_BYTES>>>(bias, out);
}